// round 16
// baseline (speedup 1.0000x reference)
#include <cuda_runtime.h>
#include <math.h>

// Geometry: x (2,1,160,160,16), q/lambda (2,3,160,160,16), f32, C-order.
#define PP 2
#define XD 160
#define YD 160
#define LPB (XD*YD)
#define NV (PP*LPB*4)        // float4 count in x-shaped array = 204800
#define T_ITERS 48
#define TX 8
#define TY 8
#define NBX (XD/TX)          // 20
#define NBY (YD/TY)          // 20
#define NBLK (PP*NBX*NBY)    // 800
#define NTHR (TX*TY*4)       // 256
#define QS 32767.0f
#define FPAD 32              // one 128B line per flag
#define SCATTER 83           // coprime to 400: co-resident blocks far apart

// Only boundary xbar crosses blocks -> double-buffered global (edges only used).
__device__ float4 g_xbg[2][NV];
__device__ unsigned int g_flags[NBLK*FPAD];

__global__ void kreset() {
    int i = blockIdx.x*blockDim.x + threadIdx.x;
    if (i < NBLK) g_flags[i*FPAD] = 0u;
}

__device__ __forceinline__ unsigned int ld_acq(const unsigned int* p) {
    unsigned int v;
    asm volatile("ld.acquire.gpu.global.u32 %0, [%1];" : "=r"(v) : "l"(p) : "memory");
    return v;
}
__device__ __forceinline__ void st_rel(unsigned int* p, unsigned int v) {
    asm volatile("st.release.gpu.global.u32 [%0], %1;" :: "l"(p), "r"(v) : "memory");
}

__device__ __forceinline__ float shfl_quad(float v, int lane, int delta4) {
    int src = (lane & ~3) | ((lane + delta4) & 3);
    return __shfl_sync(0xffffffffu, v, src);
}
__device__ __forceinline__ int shfl_quad_i(int v, int lane, int delta4) {
    int src = (lane & ~3) | ((lane + delta4) & 3);
    return __shfl_sync(0xffffffffu, v, src);
}
__device__ __forceinline__ float4 f4sub(float4 a, float4 b) {
    return make_float4(a.x-b.x, a.y-b.y, a.z-b.z, a.w-b.w);
}

struct I4 { int a, b, c, d; };
__device__ __forceinline__ I4 unpk(uint2 u) {
    I4 r;
    r.a = ((int)(u.x << 16)) >> 16;
    r.b = ((int)u.x) >> 16;
    r.c = ((int)(u.y << 16)) >> 16;
    r.d = ((int)u.y) >> 16;
    return r;
}
__device__ __forceinline__ uint2 lam2pk(float4 l) {
    int a = __float2int_rn(l.x * QS), b = __float2int_rn(l.y * QS);
    int c = __float2int_rn(l.z * QS), d = __float2int_rn(l.w * QS);
    uint2 u;
    u.x = ((unsigned)a & 0xffffu) | ((unsigned)b << 16);
    u.y = ((unsigned)c & 0xffffu) | ((unsigned)d << 16);
    return u;
}

// R8's proven qstep (cvt.rni.sat on XU pipe). Deterministic across paths.
__device__ __forceinline__ uint2 qstep_p(uint2 Q, uint2 L, float4 g, float ss) {
    short d0, d1, d2, d3;
    asm("cvt.rni.sat.s16.f32 %0, %1;" : "=h"(d0) : "f"(ss * g.x));
    asm("cvt.rni.sat.s16.f32 %0, %1;" : "=h"(d1) : "f"(ss * g.y));
    asm("cvt.rni.sat.s16.f32 %0, %1;" : "=h"(d2) : "f"(ss * g.z));
    asm("cvt.rni.sat.s16.f32 %0, %1;" : "=h"(d3) : "f"(ss * g.w));
    unsigned int lo, hi;
    asm("mov.b32 %0, {%1,%2};" : "=r"(lo) : "h"(d0), "h"(d1));
    asm("mov.b32 %0, {%1,%2};" : "=r"(hi) : "h"(d2), "h"(d3));
    uint2 r;
    r.x = __vmaxs2(__vmins2(__vaddss2(Q.x, lo), L.x), __vsubss2(0u, L.x));
    r.y = __vmaxs2(__vmins2(__vaddss2(Q.y, hi), L.y), __vsubss2(0u, L.y));
    return r;
}

__global__ void __launch_bounds__(NTHR, 6) kpersist(
    const float4* __restrict__ xn, const float4* __restrict__ lam,
    float4* __restrict__ out,
    float sigma, float sigma_s, float inv1ps, float tau, float tau_s, float theta)
{
    __shared__ float4 sxb[TX][TY][4];        // xbar tile (current gen)
    __shared__ float4 sxn[NTHR];             // noisy input (constant)
    __shared__ uint2  slam[2*NTHR];          // lambda_0/1 packed (lambda_2 in regs)
    __shared__ uint2  sq0[TX+1][TY][4];      // Q0' with left halo at [0]
    __shared__ uint2  sq1h[TX][4];           // Q1 halo col (y-dir uses shfl)

    int bid = blockIdx.x;
    // Batch-interleaved scatter: adjacent bids alternate batches (independent
    // lattices) AND within a batch land SCATTER tiles apart. Pure relabeling.
    int pp  = bid & 1;
    int t   = (int)(((long long)(bid >> 1) * SCATTER) % (NBX*NBY));
    int bx  = t / NBY, by = t % NBY;
    int x0g = bx*TX, y0g = by*TY;
    int tile = pp*(NBX*NBY) + t;

    int tid  = threadIdx.x;
    int quad = tid & 3;
    int ll   = tid >> 2;           // 0..63
    int lx   = ll >> 3;            // 0..7  (== warp index)
    int ly   = ll & 7;             // 0..7
    int lane = tid & 31;

    int base   = pp * LPB;
    int gx = x0g + lx, gy = y0g + ly;
    int line2d = gx*YD + gy;
    int gid    = (base + line2d)*4 + quad;

    // Out-of-tile +1 neighbor global indices (edge threads only).
    int xti = (base + ((x0g+TX) % XD)*YD + gy)*4 + quad;
    int yti = (base + gx*YD + ((y0g+TY) % YD))*4 + quad;

    // Lattice neighbors (flag sources, indexed by TILE). Threads 0..3 spin.
    int bxm = (bx == 0) ? NBX-1 : bx-1;
    int bxp = (bx == NBX-1) ? 0 : bx+1;
    int bym = (by == 0) ? NBY-1 : by-1;
    int byp = (by == NBY-1) ? 0 : by+1;
    const unsigned int* nflag = 0;
    if      (tid == 0) nflag = &g_flags[((pp*NBX + bxm)*NBY + by )*FPAD];
    else if (tid == 1) nflag = &g_flags[((pp*NBX + bxp)*NBY + by )*FPAD];
    else if (tid == 2) nflag = &g_flags[((pp*NBX + bx )*NBY + bym)*FPAD];
    else if (tid == 3) nflag = &g_flags[((pp*NBX + bx )*NBY + byp)*FPAD];
    unsigned int* myflag = &g_flags[tile*FPAD];

    bool pub = (lx == 0) | (lx == TX-1) | (ly == 0) | (ly == TY-1);
    bool xedge = (lx == TX-1);
    bool yedge = (ly == TY-1);

    // ---- prologue ----
    float4 v   = xn[gid];
    float4 pv  = v, x0v = v, xbv = v;
    sxn[tid] = v;
    slam[tid]        = lam2pk(lam[((pp*3+0)*LPB + line2d)*4 + quad]);
    slam[NTHR + tid] = lam2pk(lam[((pp*3+1)*LPB + line2d)*4 + quad]);
    uint2 L2r = lam2pk(lam[((pp*3+2)*LPB + line2d)*4 + quad]);  // lambda_2 in regs

    uint2 Q0 = make_uint2(0u,0u), Q1 = make_uint2(0u,0u), Q2 = make_uint2(0u,0u);

    sxb[lx][ly][quad] = v;
    if (pub) g_xbg[0][gid] = v;

    // ---- halo-tracker roles (threads 0..63) ----
    int    hgid = 0;
    uint2  hQ = make_uint2(0u,0u), hL = make_uint2(0u,0u);
    float4* hsrc = 0;
    uint2*  hdst = 0;
    if (tid < 32) {                      // Q0 halo line (x0g-1, y0g+h)
        int h   = tid >> 2;
        int hx  = (x0g == 0) ? XD-1 : x0g-1;
        int h2d = hx*YD + (y0g + h);
        hgid = (base + h2d)*4 + quad;
        hL   = lam2pk(lam[((pp*3+0)*LPB + h2d)*4 + quad]);
        hsrc = &sxb[0][h][quad];
        hdst = &sq0[0][h][quad];
    } else if (tid < 64) {               // Q1 halo line (x0g+h, y0g-1)
        int h   = (tid - 32) >> 2;
        int hy  = (y0g == 0) ? YD-1 : y0g-1;
        int h2d = (x0g + h)*YD + hy;
        hgid = (base + h2d)*4 + quad;
        hL   = lam2pk(lam[((pp*3+1)*LPB + h2d)*4 + quad]);
        hsrc = &sxb[h][0][quad];
        hdst = &sq1h[h][quad];
    }

    __syncthreads();
    if (tid == 0) st_rel(myflag, 1u);    // xbar gen 0 published

    for (int k = 0; k < T_ITERS; k++) {
        const float4* gin = g_xbg[k & 1];
        unsigned int want = (unsigned int)(k + 1);

        // ===== Centralized wait: 4 threads spin, the rest sleep on BAR =====
        if (nflag) { while (ld_acq(nflag) < want) { } }
        __syncthreads();

        // ===== Phase B: gen-k neighbor reads + duals =====
        float4 xbx = xedge ? __ldcv(gin + xti) : sxb[lx+1][ly][quad];
        float4 xby = yedge ? __ldcv(gin + yti) : sxb[lx][ly+1][quad];

        float nxt = shfl_quad(xbv.x, lane, 1);
        float4 gtv = make_float4(xbv.y-xbv.x, xbv.z-xbv.y, xbv.w-xbv.z, nxt-xbv.w);
        float4 gxv = f4sub(xbx, xbv);
        float4 gyv = f4sub(xby, xbv);

        Q0 = qstep_p(Q0, slam[tid],      gxv, sigma_s); sq0[lx+1][ly][quad] = Q0;
        Q1 = qstep_p(Q1, slam[NTHR+tid], gyv, sigma_s);
        Q2 = qstep_p(Q2, L2r,            gtv, sigma_s);

        uint2 Q1u;
        Q1u.x = __shfl_up_sync(0xffffffffu, Q1.x, 4);
        Q1u.y = __shfl_up_sync(0xffffffffu, Q1.y, 4);

        // halo Q tracked locally (bitwise = neighbor's owner value)
        if (tid < 64) {
            float4 a = __ldcv(gin + hgid);
            float4 b = *hsrc;
            hQ = qstep_p(hQ, hL, f4sub(b, a), sigma_s);
            *hdst = hQ;
        }

        // p update (registers only)
        float4 xnv = sxn[tid];
        pv.x = (pv.x + sigma*(xbv.x - xnv.x)) * inv1ps;
        pv.y = (pv.y + sigma*(xbv.y - xnv.y)) * inv1ps;
        pv.z = (pv.z + sigma*(xbv.z - xnv.z)) * inv1ps;
        pv.w = (pv.w + sigma*(xbv.w - xnv.w)) * inv1ps;

        __syncthreads();   // sq0/sq1h ready; also orders sxb read(k)->write(k+1)

        uint2 q0mp = sq0[lx][ly][quad];
        uint2 q1mp = (ly == 0) ? sq1h[lx][quad] : Q1u;

        I4 q0  = unpk(Q0),   q1  = unpk(Q1),   q2 = unpk(Q2);
        I4 q0m = unpk(q0mp), q1m = unpk(q1mp);
        int prevw = shfl_quad_i(q2.d, lane, -1);

        int adja = (q0m.a - q0.a) + (q1m.a - q1.a) + (prevw - q2.a);
        int adjb = (q0m.b - q0.b) + (q1m.b - q1.b) + (q2.a  - q2.b);
        int adjc = (q0m.c - q0.c) + (q1m.c - q1.c) + (q2.b  - q2.c);
        int adjd = (q0m.d - q0.d) + (q1m.d - q1.d) + (q2.c  - q2.d);

        float4 x1;
        x1.x = x0v.x - tau*pv.x - tau_s*__int2float_rn(adja);
        x1.y = x0v.y - tau*pv.y - tau_s*__int2float_rn(adjb);
        x1.z = x0v.z - tau*pv.z - tau_s*__int2float_rn(adjc);
        x1.w = x0v.w - tau*pv.w - tau_s*__int2float_rn(adjd);

        float opt = 1.0f + theta;
        float4 xbn;
        xbn.x = opt*x1.x - theta*x0v.x;
        xbn.y = opt*x1.y - theta*x0v.y;
        xbn.z = opt*x1.z - theta*x0v.z;
        xbn.w = opt*x1.w - theta*x0v.w;

        x0v = x1;
        xbv = xbn;

        if (k < T_ITERS-1) {
            if (pub) g_xbg[(k+1) & 1][gid] = xbv;   // boundary publish
            sxb[lx][ly][quad] = xbv;
            __syncthreads();
            if (tid == 0) st_rel(myflag, (unsigned int)(k + 2));
        }
    }

    out[gid] = x0v;                        // x1 after 48 iterations
}

extern "C" void kernel_launch(void* const* d_in, const int* in_sizes, int n_in,
                              void* d_out, int out_size) {
    const float4* x   = (const float4*)d_in[0];
    const float4* lam = (const float4*)d_in[1];
    float4* out = (float4*)d_out;

    cudaFuncSetAttribute(kpersist, cudaFuncAttributePreferredSharedMemoryCarveout, 100);

    float L     = sqrtf(13.0f);
    float s10   = 1.0f / (1.0f + expf(-10.0f));
    float sigma = s10 / L;
    float tau   = s10 / L;
    float theta = s10;
    float inv1ps  = 1.0f / (1.0f + sigma);
    float sigma_s = sigma * QS;
    float tau_s   = tau / QS;

    kreset<<<1, NBLK>>>();
    kpersist<<<NBLK, NTHR>>>(x, lam, out, sigma, sigma_s, inv1ps, tau, tau_s, theta);
}

// round 17
// speedup vs baseline: 1.0334x; 1.0334x over previous
#include <cuda_runtime.h>
#include <math.h>

// Geometry: x (2,1,160,160,16), q/lambda (2,3,160,160,16), f32, C-order.
#define PP 2
#define XD 160
#define YD 160
#define LPB (XD*YD)
#define NV (PP*LPB*4)        // float4 count in x-shaped array = 204800
#define T_ITERS 48
#define TX 8                 // tile extent in x (lines)
#define TY 4                 // tile extent in y (lines)
#define NBX (XD/TX)          // 20
#define NBY (YD/TY)          // 40
#define TPB (NBX*NBY)        // 800 tiles per batch
#define NBLK (PP*TPB)        // 1600
#define NTHR (TX*TY*4)       // 128
#define QS 32767.0f
#define FPAD 32              // one 128B line per flag
#define SCATTER 83           // coprime to 800: co-resident blocks far apart

// Only boundary xbar crosses blocks -> double-buffered global (edges only used).
__device__ float4 g_xbg[2][NV];
__device__ unsigned int g_flags[NBLK*FPAD];

__global__ void kreset() {
    int i = blockIdx.x*blockDim.x + threadIdx.x;
    if (i < NBLK) g_flags[i*FPAD] = 0u;
}

__device__ __forceinline__ unsigned int ld_acq(const unsigned int* p) {
    unsigned int v;
    asm volatile("ld.acquire.gpu.global.u32 %0, [%1];" : "=r"(v) : "l"(p) : "memory");
    return v;
}
__device__ __forceinline__ void st_rel(unsigned int* p, unsigned int v) {
    asm volatile("st.release.gpu.global.u32 [%0], %1;" :: "l"(p), "r"(v) : "memory");
}

__device__ __forceinline__ float shfl_quad(float v, int lane, int delta4) {
    int src = (lane & ~3) | ((lane + delta4) & 3);
    return __shfl_sync(0xffffffffu, v, src);
}
__device__ __forceinline__ int shfl_quad_i(int v, int lane, int delta4) {
    int src = (lane & ~3) | ((lane + delta4) & 3);
    return __shfl_sync(0xffffffffu, v, src);
}
__device__ __forceinline__ float4 f4sub(float4 a, float4 b) {
    return make_float4(a.x-b.x, a.y-b.y, a.z-b.z, a.w-b.w);
}

struct I4 { int a, b, c, d; };
__device__ __forceinline__ I4 unpk(uint2 u) {
    I4 r;
    r.a = ((int)(u.x << 16)) >> 16;
    r.b = ((int)u.x) >> 16;
    r.c = ((int)(u.y << 16)) >> 16;
    r.d = ((int)u.y) >> 16;
    return r;
}
__device__ __forceinline__ uint2 lam2pk(float4 l) {
    int a = __float2int_rn(l.x * QS), b = __float2int_rn(l.y * QS);
    int c = __float2int_rn(l.z * QS), d = __float2int_rn(l.w * QS);
    uint2 u;
    u.x = ((unsigned)a & 0xffffu) | ((unsigned)b << 16);
    u.y = ((unsigned)c & 0xffffu) | ((unsigned)d << 16);
    return u;
}

// R8's proven qstep (cvt.rni.sat on XU pipe). Deterministic across paths.
__device__ __forceinline__ uint2 qstep_p(uint2 Q, uint2 L, float4 g, float ss) {
    short d0, d1, d2, d3;
    asm("cvt.rni.sat.s16.f32 %0, %1;" : "=h"(d0) : "f"(ss * g.x));
    asm("cvt.rni.sat.s16.f32 %0, %1;" : "=h"(d1) : "f"(ss * g.y));
    asm("cvt.rni.sat.s16.f32 %0, %1;" : "=h"(d2) : "f"(ss * g.z));
    asm("cvt.rni.sat.s16.f32 %0, %1;" : "=h"(d3) : "f"(ss * g.w));
    unsigned int lo, hi;
    asm("mov.b32 %0, {%1,%2};" : "=r"(lo) : "h"(d0), "h"(d1));
    asm("mov.b32 %0, {%1,%2};" : "=r"(hi) : "h"(d2), "h"(d3));
    uint2 r;
    r.x = __vmaxs2(__vmins2(__vaddss2(Q.x, lo), L.x), __vsubss2(0u, L.x));
    r.y = __vmaxs2(__vmins2(__vaddss2(Q.y, hi), L.y), __vsubss2(0u, L.y));
    return r;
}

__global__ void __launch_bounds__(NTHR, 12) kpersist(
    const float4* __restrict__ xn, const float4* __restrict__ lam,
    float4* __restrict__ out,
    float sigma, float sigma_s, float inv1ps, float tau, float tau_s, float theta)
{
    __shared__ float4 sxb[TX][TY][4];        // xbar tile (current gen)
    __shared__ float4 sxn[NTHR];             // noisy input (constant)
    __shared__ uint2  slam[2*NTHR];          // lambda_0/1 (lambda_2 in regs)
    __shared__ uint2  sq0[TX+1][TY][4];      // Q0' with left halo at [0]
    __shared__ uint2  sq1h[TX][4];           // Q1 halo col (y-dir uses shfl)

    int bid = blockIdx.x;
    int pp  = bid / TPB;
    // Within-batch scatter (R15-proven): co-resident blocks land far apart.
    int t   = (int)(((long long)(bid % TPB) * SCATTER) % TPB);
    int bx  = t / NBY, by = t % NBY;
    int x0g = bx*TX, y0g = by*TY;
    int tile = pp*TPB + t;

    int tid  = threadIdx.x;
    int quad = tid & 3;
    int ll   = tid >> 2;           // 0..31
    int lx   = ll >> 2;            // 0..7
    int ly   = ll & 3;             // 0..3
    int lane = tid & 31;

    int base   = pp * LPB;
    int gx = x0g + lx, gy = y0g + ly;
    int line2d = gx*YD + gy;
    int gid    = (base + line2d)*4 + quad;

    // Out-of-tile +1 neighbor global indices (edge threads only).
    int xti = (base + ((x0g+TX) % XD)*YD + gy)*4 + quad;
    int yti = (base + gx*YD + ((y0g+TY) % YD))*4 + quad;

    // Lattice neighbors (flag sources, indexed by TILE). Threads 0..3 spin.
    int bxm = (bx == 0) ? NBX-1 : bx-1;
    int bxp = (bx == NBX-1) ? 0 : bx+1;
    int bym = (by == 0) ? NBY-1 : by-1;
    int byp = (by == NBY-1) ? 0 : by+1;
    const unsigned int* nflag = 0;
    if      (tid == 0) nflag = &g_flags[(pp*TPB + bxm*NBY + by )*FPAD];
    else if (tid == 1) nflag = &g_flags[(pp*TPB + bxp*NBY + by )*FPAD];
    else if (tid == 2) nflag = &g_flags[(pp*TPB + bx *NBY + bym)*FPAD];
    else if (tid == 3) nflag = &g_flags[(pp*TPB + bx *NBY + byp)*FPAD];
    unsigned int* myflag = &g_flags[tile*FPAD];

    bool pub = (lx == 0) | (lx == TX-1) | (ly == 0) | (ly == TY-1);
    bool xedge = (lx == TX-1);
    bool yedge = (ly == TY-1);

    // ---- prologue ----
    float4 v   = xn[gid];
    float4 pv  = v, x0v = v, xbv = v;
    sxn[tid] = v;
    slam[tid]        = lam2pk(lam[((pp*3+0)*LPB + line2d)*4 + quad]);
    slam[NTHR + tid] = lam2pk(lam[((pp*3+1)*LPB + line2d)*4 + quad]);
    uint2 L2r = lam2pk(lam[((pp*3+2)*LPB + line2d)*4 + quad]);  // lambda_2 in regs

    uint2 Q0 = make_uint2(0u,0u), Q1 = make_uint2(0u,0u), Q2 = make_uint2(0u,0u);

    sxb[lx][ly][quad] = v;
    if (pub) g_xbg[0][gid] = v;

    // ---- halo-tracker roles ----
    // threads 0..15   : Q0 halo line (x0g-1, y0g+h), h = tid>>2 in 0..3
    // threads 32..63  : Q1 halo line (x0g+h, y0g-1), h = (tid-32)>>2 in 0..7
    int    hgid = 0;
    uint2  hQ = make_uint2(0u,0u), hL = make_uint2(0u,0u);
    float4* hsrc = 0;
    uint2*  hdst = 0;
    if (tid < 16) {
        int h   = tid >> 2;
        int hx  = (x0g == 0) ? XD-1 : x0g-1;
        int h2d = hx*YD + (y0g + h);
        hgid = (base + h2d)*4 + quad;
        hL   = lam2pk(lam[((pp*3+0)*LPB + h2d)*4 + quad]);
        hsrc = &sxb[0][h][quad];
        hdst = &sq0[0][h][quad];
    } else if (tid >= 32 && tid < 64) {
        int h   = (tid - 32) >> 2;
        int hy  = (y0g == 0) ? YD-1 : y0g-1;
        int h2d = (x0g + h)*YD + hy;
        hgid = (base + h2d)*4 + quad;
        hL   = lam2pk(lam[((pp*3+1)*LPB + h2d)*4 + quad]);
        hsrc = &sxb[h][0][quad];
        hdst = &sq1h[h][quad];
    }
    bool is_halo = (tid < 16) | (tid >= 32 && tid < 64);

    __syncthreads();
    if (tid == 0) st_rel(myflag, 1u);    // xbar gen 0 published

    for (int k = 0; k < T_ITERS; k++) {
        const float4* gin = g_xbg[k & 1];
        unsigned int want = (unsigned int)(k + 1);

        // ===== Centralized wait: 4 threads spin, the rest sleep on BAR =====
        if (nflag) { while (ld_acq(nflag) < want) { } }
        __syncthreads();

        // ===== Phase B: gen-k neighbor reads + duals =====
        float4 xbx = xedge ? __ldcv(gin + xti) : sxb[lx+1][ly][quad];
        float4 xby = yedge ? __ldcv(gin + yti) : sxb[lx][ly+1][quad];

        float nxt = shfl_quad(xbv.x, lane, 1);
        float4 gtv = make_float4(xbv.y-xbv.x, xbv.z-xbv.y, xbv.w-xbv.z, nxt-xbv.w);
        float4 gxv = f4sub(xbx, xbv);
        float4 gyv = f4sub(xby, xbv);

        Q0 = qstep_p(Q0, slam[tid],      gxv, sigma_s); sq0[lx+1][ly][quad] = Q0;
        Q1 = qstep_p(Q1, slam[NTHR+tid], gyv, sigma_s);
        Q2 = qstep_p(Q2, L2r,            gtv, sigma_s);

        uint2 Q1u;
        Q1u.x = __shfl_up_sync(0xffffffffu, Q1.x, 4);
        Q1u.y = __shfl_up_sync(0xffffffffu, Q1.y, 4);

        // halo Q tracked locally (bitwise = neighbor's owner value)
        if (is_halo) {
            float4 a = __ldcv(gin + hgid);
            float4 b = *hsrc;
            hQ = qstep_p(hQ, hL, f4sub(b, a), sigma_s);
            *hdst = hQ;
        }

        // p update (registers only)
        float4 xnv = sxn[tid];
        pv.x = (pv.x + sigma*(xbv.x - xnv.x)) * inv1ps;
        pv.y = (pv.y + sigma*(xbv.y - xnv.y)) * inv1ps;
        pv.z = (pv.z + sigma*(xbv.z - xnv.z)) * inv1ps;
        pv.w = (pv.w + sigma*(xbv.w - xnv.w)) * inv1ps;

        __syncthreads();   // sq0/sq1h ready; also orders sxb read(k)->write(k+1)

        uint2 q0mp = sq0[lx][ly][quad];
        uint2 q1mp = (ly == 0) ? sq1h[lx][quad] : Q1u;

        I4 q0  = unpk(Q0),   q1  = unpk(Q1),   q2 = unpk(Q2);
        I4 q0m = unpk(q0mp), q1m = unpk(q1mp);
        int prevw = shfl_quad_i(q2.d, lane, -1);

        int adja = (q0m.a - q0.a) + (q1m.a - q1.a) + (prevw - q2.a);
        int adjb = (q0m.b - q0.b) + (q1m.b - q1.b) + (q2.a  - q2.b);
        int adjc = (q0m.c - q0.c) + (q1m.c - q1.c) + (q2.b  - q2.c);
        int adjd = (q0m.d - q0.d) + (q1m.d - q1.d) + (q2.c  - q2.d);

        float4 x1;
        x1.x = x0v.x - tau*pv.x - tau_s*__int2float_rn(adja);
        x1.y = x0v.y - tau*pv.y - tau_s*__int2float_rn(adjb);
        x1.z = x0v.z - tau*pv.z - tau_s*__int2float_rn(adjc);
        x1.w = x0v.w - tau*pv.w - tau_s*__int2float_rn(adjd);

        float opt = 1.0f + theta;
        float4 xbn;
        xbn.x = opt*x1.x - theta*x0v.x;
        xbn.y = opt*x1.y - theta*x0v.y;
        xbn.z = opt*x1.z - theta*x0v.z;
        xbn.w = opt*x1.w - theta*x0v.w;

        x0v = x1;
        xbv = xbn;

        if (k < T_ITERS-1) {
            if (pub) g_xbg[(k+1) & 1][gid] = xbv;   // boundary publish
            sxb[lx][ly][quad] = xbv;
            __syncthreads();
            if (tid == 0) st_rel(myflag, (unsigned int)(k + 2));
        }
    }

    out[gid] = x0v;                        // x1 after 48 iterations
}

extern "C" void kernel_launch(void* const* d_in, const int* in_sizes, int n_in,
                              void* d_out, int out_size) {
    const float4* x   = (const float4*)d_in[0];
    const float4* lam = (const float4*)d_in[1];
    float4* out = (float4*)d_out;

    cudaFuncSetAttribute(kpersist, cudaFuncAttributePreferredSharedMemoryCarveout, 100);

    float L     = sqrtf(13.0f);
    float s10   = 1.0f / (1.0f + expf(-10.0f));
    float sigma = s10 / L;
    float tau   = s10 / L;
    float theta = s10;
    float inv1ps  = 1.0f / (1.0f + sigma);
    float sigma_s = sigma * QS;
    float tau_s   = tau / QS;

    kreset<<<(NBLK + 255)/256, 256>>>();
    kpersist<<<NBLK, NTHR>>>(x, lam, out, sigma, sigma_s, inv1ps, tau, tau_s, theta);
}